// round 14
// baseline (speedup 1.0000x reference)
#include <cuda_runtime.h>
#include <cuda_fp16.h>
#include <cstdint>

// FineMatching, persistent producer/consumer version.
//   sims = x0·x1^T/128 (fp16 two-limb, 3 plane products == 3xTF32 accuracy)
//   heatmap = softmax_l * softmax_s ; masked argmax -> idx/biases
// d_out (f32): [ heatmap M*4096 | idx_l M | idx_s M | biases0 2M | biases1 2M ]
//
// Round-14: grid = #SMs, 256 threads. Warps 4-7 stage match k+1 into buffer
// (k+1)&1 (LDG -> limb split -> swizzled planes) while warps 0-3 run the
// round-13 GEMM+epilogue on buffer k&1. Named-barrier double-buffer handshake.
// Goal: DRAM streaming never pauses (52% -> ~80% of 8TB/s).

#define NTHREADS 256
#define BUF_STRIDE 65536
// plane offsets within a buffer
#define P_AP2 16384
#define P_BP1 32768
// shared epilogue scratch (after both buffers)
#define OFF_RP  131072              // row partials 64 x 4 f32
#define OFF_CS  (OFF_RP + 1024)     // csum 64
#define OFF_CI  (OFF_CS + 256)      // cinv 64
#define OFF_RI  (OFF_CI + 256)      // rinv 64
#define OFF_RV  (OFF_RI + 256)      // 4 f32
#define OFF_RX  (OFF_RV + 16)       // 4 i32
#define SMEM_BYTES (OFF_RX + 16)

#define BARS(id)  asm volatile("bar.sync %0, 256;"   :: "r"(id) : "memory")
#define BARA(id)  asm volatile("bar.arrive %0, 256;" :: "r"(id) : "memory")
#define BARC()    asm volatile("bar.sync 5, 128;"    ::: "memory")

__device__ __forceinline__ uint32_t smem_u32(const void* p) {
    uint32_t a;
    asm("{ .reg .u64 t; cvta.to.shared.u64 t, %1; cvt.u32.u64 %0, t; }" : "=r"(a) : "l"(p));
    return a;
}

__device__ __forceinline__ uint32_t h2_bits(__half2 h) {
    union { __half2 h; uint32_t u; } c;
    c.h = h;
    return c.u;
}

__device__ __forceinline__ void ldsm_x4(uint32_t& r0, uint32_t& r1, uint32_t& r2,
                                        uint32_t& r3, uint32_t addr) {
    asm volatile("ldmatrix.sync.aligned.m8n8.x4.shared.b16 {%0,%1,%2,%3}, [%4];"
                 : "=r"(r0), "=r"(r1), "=r"(r2), "=r"(r3) : "r"(addr));
}

__device__ __forceinline__ void mma_f16(float& d0, float& d1, float& d2, float& d3,
                                        uint32_t a0, uint32_t a1, uint32_t a2, uint32_t a3,
                                        uint32_t b0, uint32_t b1) {
    asm volatile(
        "mma.sync.aligned.m16n8k16.row.col.f32.f16.f16.f32 "
        "{%0,%1,%2,%3}, {%4,%5,%6,%7}, {%8,%9}, {%0,%1,%2,%3};"
        : "+f"(d0), "+f"(d1), "+f"(d2), "+f"(d3)
        : "r"(a0), "r"(a1), "r"(a2), "r"(a3), "r"(b0), "r"(b1));
}

__device__ __forceinline__ bool inner_mask(int p) {
    int y = p >> 3, x = p & 7;
    return (y >= 1) & (y <= 6) & (x >= 1) & (x <= 6);
}

__device__ __forceinline__ void limb4(float4 f, uint2& w1, uint2& w2) {
    float2 xy = make_float2(f.x * 256.0f, f.y * 256.0f);
    float2 zw = make_float2(f.z * 256.0f, f.w * 256.0f);
    __half2 h1a = __float22half2_rn(xy);
    __half2 h1b = __float22half2_rn(zw);
    float2 b1 = __half22float2(h1a);
    float2 b2 = __half22float2(h1b);
    __half2 h2a = __float22half2_rn(make_float2(xy.x - b1.x, xy.y - b1.y));
    __half2 h2b = __float22half2_rn(make_float2(zw.x - b2.x, zw.y - b2.y));
    w1 = make_uint2(h2_bits(h1a), h2_bits(h1b));
    w2 = make_uint2(h2_bits(h2a), h2_bits(h2b));
}

__global__ void __launch_bounds__(NTHREADS, 1)
fm_kernel(const float* __restrict__ x0, const float* __restrict__ x1,
          float* __restrict__ hm, float* __restrict__ oil,
          float* __restrict__ ois, float* __restrict__ ob0,
          float* __restrict__ ob1, int Mtot) {
    extern __shared__ char sm[];
    float* rowpart = (float*)(sm + OFF_RP);
    float* csum_s  = (float*)(sm + OFF_CS);
    float* cinv_s  = (float*)(sm + OFF_CI);
    float* rinv_s  = (float*)(sm + OFF_RI);
    float* redv    = (float*)(sm + OFF_RV);
    int*   redi    = (int*)(sm + OFF_RX);

    const int tid  = threadIdx.x;
    const int warp = tid >> 5;
    const int lane = tid & 31;
    const int bid  = blockIdx.x;
    const int GD   = gridDim.x;

    if (warp >= 4) {
        // ================= producer crew (warps 4-7) =================
        const int t = tid - 128;
        int k = 0;
        for (int m = bid; m < Mtot; m += GD, k++) {
            const int b = k & 1;
            if (k >= 2) BARS(3 + b);                 // wait buffer free
            char* bp = sm + b * BUF_STRIDE;
            const float4* p0 = (const float4*)(x0 + (size_t)m * 8192);
            const float4* p1 = (const float4*)(x1 + (size_t)m * 8192);
#pragma unroll
            for (int it = 0; it < 16; it++) {
                int i   = t + it * 128;
                int row = i >> 5;
                int q   = i & 31;
                uint32_t off = (uint32_t)(row * 256) +
                               (((uint32_t)(q * 8)) ^ (uint32_t)((row & 7) << 4));
                uint2 w1, w2;
                limb4(p0[i], w1, w2);
                *(uint2*)(bp + off)           = w1;   // A h1
                *(uint2*)(bp + P_AP2 + off)   = w2;   // A h2
                limb4(p1[i], w1, w2);
                *(uint2*)(bp + P_BP1 + off)         = w1;   // B g1
                *(uint2*)(bp + P_BP1 + 16384 + off) = w2;   // B g2
            }
            asm volatile("membar.cta;" ::: "memory");
            BARA(1 + b);                             // buffer ready
        }
        return;
    }

    // ================= consumer crew (warps 0-3) =================
    const int g   = lane >> 2;
    const int tig = lane & 3;
    const uint32_t smb = smem_u32(sm);

    // loop-invariant fragment addressing
    const int qm = lane >> 3;
    const int rm = lane & 7;
    const uint32_t kq = (uint32_t)((qm >> 1) << 4);
    uint32_t aoff[4], axm[4];
#pragma unroll
    for (int mt = 0; mt < 4; mt++) {
        int row = mt * 16 + ((qm & 1) << 3) + rm;
        aoff[mt] = (uint32_t)(row * 256);
        axm[mt]  = (uint32_t)((row & 7) << 4);
    }
    uint32_t b1off[2], bswz[2];
#pragma unroll
    for (int nt = 0; nt < 2; nt++) {
        int srow = warp * 16 + nt * 8 + g;
        b1off[nt] = (uint32_t)(P_BP1 + srow * 256 + tig * 4);
        bswz[nt]  = (uint32_t)((srow & 7) << 4);
    }
    bool mcol[2][2];
#pragma unroll
    for (int nt = 0; nt < 2; nt++) {
        int c = warp * 16 + nt * 8 + 2 * tig;
        mcol[nt][0] = inner_mask(c);
        mcol[nt][1] = inner_mask(c + 1);
    }

    int k = 0;
    for (int m = bid; m < Mtot; m += GD, k++) {
        const int b = k & 1;
        BARS(1 + b);                                 // wait buffer ready
        const uint32_t bo = (uint32_t)(b * BUF_STRIDE);

        float acc[4][2][4];
#pragma unroll
        for (int mt = 0; mt < 4; mt++)
#pragma unroll
            for (int nt = 0; nt < 2; nt++)
#pragma unroll
                for (int qq = 0; qq < 4; qq++) acc[mt][nt][qq] = 0.0f;

#pragma unroll
        for (int kt = 0; kt < 8; kt++) {
            uint32_t c0 = (uint32_t)(kt << 5);
            uint32_t c1 = c0 + 16;
            uint32_t q10[2], q11[2], q20[2], q21[2];
#pragma unroll
            for (int nt = 0; nt < 2; nt++) {
                const char* bb = sm + bo + b1off[nt];
                q10[nt] = *(const uint32_t*)(bb + (c0 ^ bswz[nt]));
                q11[nt] = *(const uint32_t*)(bb + (c1 ^ bswz[nt]));
                q20[nt] = *(const uint32_t*)(bb + 16384 + (c0 ^ bswz[nt]));
                q21[nt] = *(const uint32_t*)(bb + 16384 + (c1 ^ bswz[nt]));
            }
#pragma unroll
            for (int mt = 0; mt < 4; mt++) {
                uint32_t ad = smb + bo + aoff[mt] + ((c0 + kq) ^ axm[mt]);
                uint32_t a10, a11, a12, a13, a20, a21, a22, a23;
                ldsm_x4(a10, a11, a12, a13, ad);            // A h1
                ldsm_x4(a20, a21, a22, a23, ad + P_AP2);    // A h2
#pragma unroll
                for (int nt = 0; nt < 2; nt++) {
                    float* d = acc[mt][nt];
                    mma_f16(d[0], d[1], d[2], d[3], a10, a11, a12, a13, q10[nt], q11[nt]);
                    mma_f16(d[0], d[1], d[2], d[3], a10, a11, a12, a13, q20[nt], q21[nt]);
                    mma_f16(d[0], d[1], d[2], d[3], a20, a21, a22, a23, q10[nt], q11[nt]);
                }
            }
        }
        BARA(3 + b);                                 // buffer free (reads done)

        // ---- epilogue: e = exp(acc * 2^-23) ----
        const float invs = 1.0f / 8388608.0f;
#pragma unroll
        for (int mt = 0; mt < 4; mt++)
#pragma unroll
            for (int nt = 0; nt < 2; nt++)
#pragma unroll
                for (int qq = 0; qq < 4; qq++)
                    acc[mt][nt][qq] = __expf(acc[mt][nt][qq] * invs);

#pragma unroll
        for (int mt = 0; mt < 4; mt++) {
            float r0 = acc[mt][0][0] + acc[mt][0][1] + acc[mt][1][0] + acc[mt][1][1];
            float r1 = acc[mt][0][2] + acc[mt][0][3] + acc[mt][1][2] + acc[mt][1][3];
            r0 += __shfl_xor_sync(0xffffffffu, r0, 1);
            r0 += __shfl_xor_sync(0xffffffffu, r0, 2);
            r1 += __shfl_xor_sync(0xffffffffu, r1, 1);
            r1 += __shfl_xor_sync(0xffffffffu, r1, 2);
            if (tig == 0) {
                rowpart[(mt * 16 + g) * 4 + warp]     = r0;
                rowpart[(mt * 16 + g + 8) * 4 + warp] = r1;
            }
        }
#pragma unroll
        for (int nt = 0; nt < 2; nt++) {
            float c0 = acc[0][nt][0] + acc[0][nt][2];
            float c1 = acc[0][nt][1] + acc[0][nt][3];
#pragma unroll
            for (int mt = 1; mt < 4; mt++) {
                c0 += acc[mt][nt][0] + acc[mt][nt][2];
                c1 += acc[mt][nt][1] + acc[mt][nt][3];
            }
            c0 += __shfl_xor_sync(0xffffffffu, c0, 4);
            c0 += __shfl_xor_sync(0xffffffffu, c0, 8);
            c0 += __shfl_xor_sync(0xffffffffu, c0, 16);
            c1 += __shfl_xor_sync(0xffffffffu, c1, 4);
            c1 += __shfl_xor_sync(0xffffffffu, c1, 8);
            c1 += __shfl_xor_sync(0xffffffffu, c1, 16);
            if (g == 0)
                *(float2*)(csum_s + warp * 16 + nt * 8 + 2 * tig) = make_float2(c0, c1);
        }
        BARC();
        if (tid < 64) {
            const float4* rp = (const float4*)(rowpart + tid * 4);
            float4 p = rp[0];
            rinv_s[tid] = 1.0f / ((p.x + p.y) + (p.z + p.w));
        } else {
            int c = tid - 64;
            cinv_s[c] = 1.0f / csum_s[c];
        }
        BARC();

        float rin[4][2];
#pragma unroll
        for (int mt = 0; mt < 4; mt++) {
            rin[mt][0] = rinv_s[mt * 16 + g];
            rin[mt][1] = rinv_s[mt * 16 + g + 8];
        }
        float2 cin[2];
#pragma unroll
        for (int nt = 0; nt < 2; nt++)
            cin[nt] = *(const float2*)(cinv_s + warp * 16 + nt * 8 + 2 * tig);

        float bestv = -1.0f;
        int   besti = 0;
        float* hmbase = hm + (size_t)m * 4096;
#pragma unroll
        for (int mt = 0; mt < 4; mt++) {
            int row0 = mt * 16 + g;
            bool mr0 = inner_mask(row0);
            bool mr1 = inner_mask(row0 + 8);
#pragma unroll
            for (int nt = 0; nt < 2; nt++) {
                int col0 = warp * 16 + nt * 8 + 2 * tig;
                float h0 = acc[mt][nt][0] * acc[mt][nt][0] * rin[mt][0] * cin[nt].x;
                float h1 = acc[mt][nt][1] * acc[mt][nt][1] * rin[mt][0] * cin[nt].y;
                float h2 = acc[mt][nt][2] * acc[mt][nt][2] * rin[mt][1] * cin[nt].x;
                float h3 = acc[mt][nt][3] * acc[mt][nt][3] * rin[mt][1] * cin[nt].y;
                *(float2*)(hmbase + row0 * 64 + col0)       = make_float2(h0, h1);
                *(float2*)(hmbase + (row0 + 8) * 64 + col0) = make_float2(h2, h3);
                if (mr0) {
                    if (mcol[nt][0]) {
                        int fi = (row0 << 6) | col0;
                        if (h0 > bestv || (h0 == bestv && fi < besti)) { bestv = h0; besti = fi; }
                    }
                    if (mcol[nt][1]) {
                        int fi = (row0 << 6) | (col0 + 1);
                        if (h1 > bestv || (h1 == bestv && fi < besti)) { bestv = h1; besti = fi; }
                    }
                }
                if (mr1) {
                    if (mcol[nt][0]) {
                        int fi = ((row0 + 8) << 6) | col0;
                        if (h2 > bestv || (h2 == bestv && fi < besti)) { bestv = h2; besti = fi; }
                    }
                    if (mcol[nt][1]) {
                        int fi = ((row0 + 8) << 6) | (col0 + 1);
                        if (h3 > bestv || (h3 == bestv && fi < besti)) { bestv = h3; besti = fi; }
                    }
                }
            }
        }

#pragma unroll
        for (int off = 16; off >= 1; off >>= 1) {
            float ov = __shfl_xor_sync(0xffffffffu, bestv, off);
            int   oi = __shfl_xor_sync(0xffffffffu, besti, off);
            if (ov > bestv || (ov == bestv && oi < besti)) { bestv = ov; besti = oi; }
        }
        if (lane == 0) { redv[warp] = bestv; redi[warp] = besti; }
        BARC();
        if (tid == 0) {
            float bv = redv[0];
            int   bx = redi[0];
#pragma unroll
            for (int w = 1; w < 4; w++) {
                float ov = redv[w];
                int   oi = redi[w];
                if (ov > bv || (ov == bv && oi < bx)) { bv = ov; bx = oi; }
            }
            int il = bx >> 6;
            int is = bx & 63;
            oil[m] = (float)il;
            ois[m] = (float)is;
            ob0[2 * m + 0] = (float)(il & 7) - 3.5f;
            ob0[2 * m + 1] = (float)(il >> 3) - 3.5f;
            ob1[2 * m + 0] = (float)(is & 7) - 3.5f;
            ob1[2 * m + 1] = (float)(is >> 3) - 3.5f;
        }
    }
}

extern "C" void kernel_launch(void* const* d_in, const int* in_sizes, int n_in,
                              void* d_out, int out_size) {
    const float* x0 = (const float*)d_in[0];
    const float* x1 = (const float*)d_in[1];
    const int M = in_sizes[0] / (64 * 128);

    float* out = (float*)d_out;
    float* hm  = out;
    float* oil = hm + (size_t)M * 4096;
    float* ois = oil + M;
    float* ob0 = ois + M;
    float* ob1 = ob0 + 2 * (size_t)M;

    int sms = 148;
    cudaDeviceGetAttribute(&sms, cudaDevAttrMultiProcessorCount, 0);
    int grid = (M < sms) ? M : sms;

    cudaFuncSetAttribute(fm_kernel, cudaFuncAttributeMaxDynamicSharedMemorySize,
                         SMEM_BYTES);
    fm_kernel<<<grid, NTHREADS, SMEM_BYTES>>>(x0, x1, hm, oil, ois, ob0, ob1, M);
}

// round 15
// speedup vs baseline: 1.2923x; 1.2923x over previous
#include <cuda_runtime.h>
#include <cuda_fp16.h>
#include <cstdint>

// FineMatching: per match m (grid.x):
//   sims[l][s] = dot(x0[m,l,:], x1[m,s,:]) / 128
//   heatmap    = softmax_l(sims) * softmax_s(sims); masked argmax -> idx/biases
//
// d_out (f32): [ heatmap M*4096 | idx_l M | idx_s M | biases0 2M | biases1 2M ]
//
// Round-15 = round-13 (best, 393us) + L2 prefetch of match m+444 (next wave's
// occupant of this CTA slot) issued right after staging, overlapping GEMM.
// Goal: keep DRAM streaming through compute troughs (52% -> ~70%).

#define NTHREADS 128
#define PF_DIST 444                  // ~concurrent CTAs (148 SMs x 3)

// ---- smem byte offsets ----
#define OFF_AP1 0                    // A h1 plane: 64 rows x 256B, XOR-swizzled
#define OFF_AP2 16384                // A h2
#define OFF_BP1 32768                // B g1
#define OFF_BP2 49152                // B g2
#define OFF_RP  65536                // row partials: 64 x 4 f32
#define OFF_CS  (OFF_RP + 1024)     // csum 64 f32
#define OFF_CI  (OFF_CS + 256)      // cinv 64 f32
#define OFF_RI  (OFF_CI + 256)      // rinv 64 f32
#define OFF_RV  (OFF_RI + 256)      // 4 f32
#define OFF_RX  (OFF_RV + 16)       // 4 i32
#define SMEM_BYTES (OFF_RX + 16)

__device__ __forceinline__ uint32_t smem_u32(const void* p) {
    uint32_t a;
    asm("{ .reg .u64 t; cvta.to.shared.u64 t, %1; cvt.u32.u64 %0, t; }" : "=r"(a) : "l"(p));
    return a;
}

__device__ __forceinline__ uint32_t h2_bits(__half2 h) {
    union { __half2 h; uint32_t u; } c;
    c.h = h;
    return c.u;
}

__device__ __forceinline__ void ldsm_x4(uint32_t& r0, uint32_t& r1, uint32_t& r2,
                                        uint32_t& r3, uint32_t addr) {
    asm volatile("ldmatrix.sync.aligned.m8n8.x4.shared.b16 {%0,%1,%2,%3}, [%4];"
                 : "=r"(r0), "=r"(r1), "=r"(r2), "=r"(r3) : "r"(addr));
}

__device__ __forceinline__ void mma_f16(float& d0, float& d1, float& d2, float& d3,
                                        uint32_t a0, uint32_t a1, uint32_t a2, uint32_t a3,
                                        uint32_t b0, uint32_t b1) {
    asm volatile(
        "mma.sync.aligned.m16n8k16.row.col.f32.f16.f16.f32 "
        "{%0,%1,%2,%3}, {%4,%5,%6,%7}, {%8,%9}, {%0,%1,%2,%3};"
        : "+f"(d0), "+f"(d1), "+f"(d2), "+f"(d3)
        : "r"(a0), "r"(a1), "r"(a2), "r"(a3), "r"(b0), "r"(b1));
}

__device__ __forceinline__ bool inner_mask(int p) {
    int y = p >> 3, x = p & 7;
    return (y >= 1) & (y <= 6) & (x >= 1) & (x <= 6);
}

// split 4 scaled floats into packed h1 (uint2) and h2 (uint2) limb pairs
__device__ __forceinline__ void limb4(float4 f, uint2& w1, uint2& w2) {
    float2 xy = make_float2(f.x * 256.0f, f.y * 256.0f);
    float2 zw = make_float2(f.z * 256.0f, f.w * 256.0f);
    __half2 h1a = __float22half2_rn(xy);
    __half2 h1b = __float22half2_rn(zw);
    float2 b1 = __half22float2(h1a);
    float2 b2 = __half22float2(h1b);
    __half2 h2a = __float22half2_rn(make_float2(xy.x - b1.x, xy.y - b1.y));
    __half2 h2b = __float22half2_rn(make_float2(zw.x - b2.x, zw.y - b2.y));
    w1 = make_uint2(h2_bits(h1a), h2_bits(h1b));
    w2 = make_uint2(h2_bits(h2a), h2_bits(h2b));
}

__global__ void __launch_bounds__(NTHREADS, 3)
fm_kernel(const float* __restrict__ x0, const float* __restrict__ x1,
          float* __restrict__ hm, float* __restrict__ oil,
          float* __restrict__ ois, float* __restrict__ ob0,
          float* __restrict__ ob1, int Mtot) {
    extern __shared__ char sm[];
    float* rowpart = (float*)(sm + OFF_RP);
    float* csum_s  = (float*)(sm + OFF_CS);
    float* cinv_s  = (float*)(sm + OFF_CI);
    float* rinv_s  = (float*)(sm + OFF_RI);
    float* redv    = (float*)(sm + OFF_RV);
    int*   redi    = (int*)(sm + OFF_RX);

    const int m    = blockIdx.x;
    const int tid  = threadIdx.x;
    const int warp = tid >> 5;
    const int lane = tid & 31;
    const int g    = lane >> 2;
    const int tig  = lane & 3;

    // ---- stage: split to limbs, write 4 planes (rows 256B, XOR-swizzled) ----
    {
        const float4* p0 = (const float4*)(x0 + (size_t)m * 8192);
        const float4* p1 = (const float4*)(x1 + (size_t)m * 8192);
#pragma unroll
        for (int it = 0; it < 16; it++) {
            int i   = tid + it * NTHREADS;      // float4 idx 0..2047
            int row = i >> 5;                   // 0..63
            int q   = i & 31;                   // float4 within row
            uint32_t off = (uint32_t)(row * 256) +
                           (((uint32_t)(q * 8)) ^ (uint32_t)((row & 7) << 4));
            uint2 w1, w2;
            limb4(p0[i], w1, w2);
            *(uint2*)(sm + OFF_AP1 + off) = w1;
            *(uint2*)(sm + OFF_AP2 + off) = w2;
            limb4(p1[i], w1, w2);
            *(uint2*)(sm + OFF_BP1 + off) = w1;
            *(uint2*)(sm + OFF_BP2 + off) = w2;
        }
    }

    // ---- L2 prefetch of the match that will occupy this slot next wave ----
    {
        int pf = m + PF_DIST;
        if (pf < Mtot) {
            const char* q0 = (const char*)(x0 + (size_t)pf * 8192);
            const char* q1 = (const char*)(x1 + (size_t)pf * 8192);
            // 32KB each = 256 lines of 128B; 128 threads x 2 lines per tensor
#pragma unroll
            for (int j = 0; j < 2; j++) {
                const char* a = q0 + (tid + j * 128) * 128;
                const char* b = q1 + (tid + j * 128) * 128;
                asm volatile("prefetch.global.L2 [%0];" :: "l"(a));
                asm volatile("prefetch.global.L2 [%0];" :: "l"(b));
            }
        }
    }
    __syncthreads();

    // ---- GEMM: warp w -> sims[0:64, w*16:(w+1)*16] ----
    float acc[4][2][4];
#pragma unroll
    for (int mt = 0; mt < 4; mt++)
#pragma unroll
        for (int nt = 0; nt < 2; nt++)
#pragma unroll
            for (int qq = 0; qq < 4; qq++) acc[mt][nt][qq] = 0.0f;

    const uint32_t smb = smem_u32(sm);
    const int qm = lane >> 3;
    const int rm = lane & 7;
    const uint32_t kq = (uint32_t)((qm >> 1) << 4);
    uint32_t abase[4], axm[4];
#pragma unroll
    for (int mt = 0; mt < 4; mt++) {
        int row = mt * 16 + ((qm & 1) << 3) + rm;
        abase[mt] = smb + OFF_AP1 + row * 256;
        axm[mt]   = (uint32_t)((row & 7) << 4);
    }
    uint32_t b1base[2], b2base[2], bswz[2];
#pragma unroll
    for (int nt = 0; nt < 2; nt++) {
        int srow = warp * 16 + nt * 8 + g;
        b1base[nt] = OFF_BP1 + srow * 256 + tig * 4;
        b2base[nt] = OFF_BP2 + srow * 256 + tig * 4;
        bswz[nt]   = (uint32_t)((srow & 7) << 4);
    }

#pragma unroll
    for (int kt = 0; kt < 8; kt++) {
        uint32_t c0 = (uint32_t)(kt << 5);
        uint32_t c1 = c0 + 16;
        // B fragments from both planes
        uint32_t q10[2], q11[2], q20[2], q21[2];
#pragma unroll
        for (int nt = 0; nt < 2; nt++) {
            q10[nt] = *(const uint32_t*)(sm + b1base[nt] + (c0 ^ bswz[nt]));
            q11[nt] = *(const uint32_t*)(sm + b1base[nt] + (c1 ^ bswz[nt]));
            q20[nt] = *(const uint32_t*)(sm + b2base[nt] + (c0 ^ bswz[nt]));
            q21[nt] = *(const uint32_t*)(sm + b2base[nt] + (c1 ^ bswz[nt]));
        }
#pragma unroll
        for (int mt = 0; mt < 4; mt++) {
            uint32_t ad = abase[mt] + ((c0 + kq) ^ axm[mt]);
            uint32_t a10, a11, a12, a13, a20, a21, a22, a23;
            ldsm_x4(a10, a11, a12, a13, ad);            // A h1
            ldsm_x4(a20, a21, a22, a23, ad + 16384);    // A h2
#pragma unroll
            for (int nt = 0; nt < 2; nt++) {
                float* d = acc[mt][nt];
                mma_f16(d[0], d[1], d[2], d[3], a10, a11, a12, a13, q10[nt], q11[nt]); // h1g1
                mma_f16(d[0], d[1], d[2], d[3], a10, a11, a12, a13, q20[nt], q21[nt]); // h1g2
                mma_f16(d[0], d[1], d[2], d[3], a20, a21, a22, a23, q10[nt], q11[nt]); // h2g1
            }
        }
    }

    // ---- epilogue in acc layout (e = exp(acc * 2^-23), no max) ----
    const float invs = 1.0f / 8388608.0f;   // 1/(128 * 2^16)
#pragma unroll
    for (int mt = 0; mt < 4; mt++)
#pragma unroll
        for (int nt = 0; nt < 2; nt++)
#pragma unroll
            for (int qq = 0; qq < 4; qq++)
                acc[mt][nt][qq] = __expf(acc[mt][nt][qq] * invs);

    // row partial sums (this warp's 16 cols) -> rowpart[row*4 + warp]
#pragma unroll
    for (int mt = 0; mt < 4; mt++) {
        float r0 = acc[mt][0][0] + acc[mt][0][1] + acc[mt][1][0] + acc[mt][1][1];
        float r1 = acc[mt][0][2] + acc[mt][0][3] + acc[mt][1][2] + acc[mt][1][3];
        r0 += __shfl_xor_sync(0xffffffffu, r0, 1);
        r0 += __shfl_xor_sync(0xffffffffu, r0, 2);
        r1 += __shfl_xor_sync(0xffffffffu, r1, 1);
        r1 += __shfl_xor_sync(0xffffffffu, r1, 2);
        if (tig == 0) {
            rowpart[(mt * 16 + g) * 4 + warp]     = r0;
            rowpart[(mt * 16 + g + 8) * 4 + warp] = r1;
        }
    }
    // col sums (all 64 rows, in-warp)
#pragma unroll
    for (int nt = 0; nt < 2; nt++) {
        float c0 = acc[0][nt][0] + acc[0][nt][2];
        float c1 = acc[0][nt][1] + acc[0][nt][3];
#pragma unroll
        for (int mt = 1; mt < 4; mt++) {
            c0 += acc[mt][nt][0] + acc[mt][nt][2];
            c1 += acc[mt][nt][1] + acc[mt][nt][3];
        }
        c0 += __shfl_xor_sync(0xffffffffu, c0, 4);
        c0 += __shfl_xor_sync(0xffffffffu, c0, 8);
        c0 += __shfl_xor_sync(0xffffffffu, c0, 16);
        c1 += __shfl_xor_sync(0xffffffffu, c1, 4);
        c1 += __shfl_xor_sync(0xffffffffu, c1, 8);
        c1 += __shfl_xor_sync(0xffffffffu, c1, 16);
        if (g == 0)
            *(float2*)(csum_s + warp * 16 + nt * 8 + 2 * tig) = make_float2(c0, c1);
    }
    __syncthreads();
    if (tid < 64) {
        const float4* rp = (const float4*)(rowpart + tid * 4);
        float4 p = rp[0];
        rinv_s[tid] = 1.0f / ((p.x + p.y) + (p.z + p.w));
    } else {
        int c = tid - 64;
        cinv_s[c] = 1.0f / csum_s[c];
    }
    __syncthreads();

    // h-pass: h = e*e*rinv[row]*cinv[col]; store + masked argmax
    float rin[4][2];
#pragma unroll
    for (int mt = 0; mt < 4; mt++) {
        rin[mt][0] = rinv_s[mt * 16 + g];
        rin[mt][1] = rinv_s[mt * 16 + g + 8];
    }
    float2 cin[2];
    bool mcol[2][2];
#pragma unroll
    for (int nt = 0; nt < 2; nt++) {
        int c = warp * 16 + nt * 8 + 2 * tig;
        cin[nt] = *(const float2*)(cinv_s + c);
        mcol[nt][0] = inner_mask(c);
        mcol[nt][1] = inner_mask(c + 1);
    }

    float bestv = -1.0f;
    int   besti = 0;
    float* hmbase = hm + (size_t)m * 4096;
#pragma unroll
    for (int mt = 0; mt < 4; mt++) {
        int row0 = mt * 16 + g;
        bool mr0 = inner_mask(row0);
        bool mr1 = inner_mask(row0 + 8);
#pragma unroll
        for (int nt = 0; nt < 2; nt++) {
            int col0 = warp * 16 + nt * 8 + 2 * tig;
            float h0 = acc[mt][nt][0] * acc[mt][nt][0] * rin[mt][0] * cin[nt].x;
            float h1 = acc[mt][nt][1] * acc[mt][nt][1] * rin[mt][0] * cin[nt].y;
            float h2 = acc[mt][nt][2] * acc[mt][nt][2] * rin[mt][1] * cin[nt].x;
            float h3 = acc[mt][nt][3] * acc[mt][nt][3] * rin[mt][1] * cin[nt].y;
            *(float2*)(hmbase + row0 * 64 + col0)       = make_float2(h0, h1);
            *(float2*)(hmbase + (row0 + 8) * 64 + col0) = make_float2(h2, h3);
            if (mr0) {
                if (mcol[nt][0]) {
                    int fi = (row0 << 6) | col0;
                    if (h0 > bestv || (h0 == bestv && fi < besti)) { bestv = h0; besti = fi; }
                }
                if (mcol[nt][1]) {
                    int fi = (row0 << 6) | (col0 + 1);
                    if (h1 > bestv || (h1 == bestv && fi < besti)) { bestv = h1; besti = fi; }
                }
            }
            if (mr1) {
                if (mcol[nt][0]) {
                    int fi = ((row0 + 8) << 6) | col0;
                    if (h2 > bestv || (h2 == bestv && fi < besti)) { bestv = h2; besti = fi; }
                }
                if (mcol[nt][1]) {
                    int fi = ((row0 + 8) << 6) | (col0 + 1);
                    if (h3 > bestv || (h3 == bestv && fi < besti)) { bestv = h3; besti = fi; }
                }
            }
        }
    }

    // block argmax (min flat idx on ties)
#pragma unroll
    for (int off = 16; off >= 1; off >>= 1) {
        float ov = __shfl_xor_sync(0xffffffffu, bestv, off);
        int   oi = __shfl_xor_sync(0xffffffffu, besti, off);
        if (ov > bestv || (ov == bestv && oi < besti)) { bestv = ov; besti = oi; }
    }
    if (lane == 0) { redv[warp] = bestv; redi[warp] = besti; }
    __syncthreads();
    if (tid == 0) {
        float bv = redv[0];
        int   bx = redi[0];
#pragma unroll
        for (int w = 1; w < 4; w++) {
            float ov = redv[w];
            int   oi = redi[w];
            if (ov > bv || (ov == bv && oi < bx)) { bv = ov; bx = oi; }
        }
        int il = bx >> 6;
        int is = bx & 63;
        oil[m] = (float)il;
        ois[m] = (float)is;
        ob0[2 * m + 0] = (float)(il & 7) - 3.5f;
        ob0[2 * m + 1] = (float)(il >> 3) - 3.5f;
        ob1[2 * m + 0] = (float)(is & 7) - 3.5f;
        ob1[2 * m + 1] = (float)(is >> 3) - 3.5f;
    }
}

extern "C" void kernel_launch(void* const* d_in, const int* in_sizes, int n_in,
                              void* d_out, int out_size) {
    const float* x0 = (const float*)d_in[0];
    const float* x1 = (const float*)d_in[1];
    const int M = in_sizes[0] / (64 * 128);

    float* out = (float*)d_out;
    float* hm  = out;
    float* oil = hm + (size_t)M * 4096;
    float* ois = oil + M;
    float* ob0 = ois + M;
    float* ob1 = ob0 + 2 * (size_t)M;

    cudaFuncSetAttribute(fm_kernel, cudaFuncAttributeMaxDynamicSharedMemorySize,
                         SMEM_BYTES);
    fm_kernel<<<M, NTHREADS, SMEM_BYTES>>>(x0, x1, hm, oil, ois, ob0, ob1, M);
}